// round 5
// baseline (speedup 1.0000x reference)
#include <cuda_runtime.h>

// ---------------------------------------------------------------------------
// 2-layer LSTM (H=512) encode (T=1024) + autoregressive decode (64 outputs),
// for batch row 255 only (the reference's output depends only on that row).
//
// Persistent kernel: 128 CTAs x 256 threads = 1024 warps.
//   Phase A (per step): warps   0..511  -> layer-1 gates (Whh1 @ h1 + Wih1*x)
//                       warps 512..1023 -> layer-2 recurrent part (Whh2 @ h2)
//   grid barrier
//   Phase B:            warps   0..511  -> layer-2 gates (Wih2 @ h1_new + part)
//   grid barrier
//
// Weights are immutable -> cached in L1 (__ldg). Mutable cross-SM state uses
// .cg (L2-only) loads/stores. The grid barrier uses acquire/release atomics
// (NOT __threadfence, which emits CCTL.IVALL on sm_103a and would flush the
// weight-resident L1 every phase).
// ---------------------------------------------------------------------------

#define GRID   128
#define TPB    256
#define HH     512
#define T_ENC  1024
#define PRED   64
#define NSTEP  (T_ENC + PRED - 1)   // 1087 LSTM steps actually executed

// ---- persistent device state (zeroed by init kernel every launch) ----------
__device__ __align__(16) float g_h1[2][HH];
__device__ __align__(16) float g_h2[2][HH];
__device__ __align__(16) float g_c1[HH];
__device__ __align__(16) float g_c2[HH];
__device__ __align__(16) float g_part2[4 * HH];
__device__ unsigned g_count;
__device__ unsigned g_epoch;

__global__ void lstm_init_kernel() {
    int i = threadIdx.x;
    for (int j = i; j < HH; j += blockDim.x) {
        g_h1[0][j] = 0.f; g_h1[1][j] = 0.f;
        g_h2[0][j] = 0.f; g_h2[1][j] = 0.f;
        g_c1[j]    = 0.f; g_c2[j]    = 0.f;
    }
    if (i == 0) { g_count = 0u; g_epoch = 0u; }
}

// ---- acquire/release primitives (generic-space PTX) ------------------------
__device__ __forceinline__ unsigned atom_add_acqrel(unsigned* p, unsigned v) {
    unsigned old;
    asm volatile("atom.acq_rel.gpu.add.u32 %0, [%1], %2;"
                 : "=r"(old) : "l"(p), "r"(v) : "memory");
    return old;
}
__device__ __forceinline__ void st_release(unsigned* p, unsigned v) {
    asm volatile("st.release.gpu.u32 [%0], %1;" :: "l"(p), "r"(v) : "memory");
}
__device__ __forceinline__ unsigned ld_acquire(unsigned* p) {
    unsigned v;
    asm volatile("ld.acquire.gpu.u32 %0, [%1];" : "=r"(v) : "l"(p) : "memory");
    return v;
}

// Grid-wide barrier. Monotonic count (no reset race); init kernel resets per run.
__device__ __forceinline__ void grid_sync(unsigned& ep) {
    __syncthreads();
    if (threadIdx.x == 0) {
        ep += 1u;
        unsigned prev = atom_add_acqrel(&g_count, 1u);
        if (prev == ep * GRID - 1u) {
            st_release(&g_epoch, ep);
        } else {
            while (ld_acquire(&g_epoch) < ep) { }
        }
    }
    __syncthreads();
}

// ---- math helpers -----------------------------------------------------------
__device__ __forceinline__ float warp_sum(float s) {
#pragma unroll
    for (int o = 16; o; o >>= 1) s += __shfl_xor_sync(0xffffffffu, s, o);
    return s;
}

// Load h (512 floats) as 4 float4 per lane from L2 (.cg: mutable, cross-SM).
__device__ __forceinline__ void load_h_cg(const float* buf, float4 h[4], int lane) {
    const float4* b4 = reinterpret_cast<const float4*>(buf);
#pragma unroll
    for (int j = 0; j < 4; j++) h[j] = __ldcg(&b4[lane + 32 * j]);
}

// Warp-cooperative dot of W[row, 0:512] with h. Weights via __ldg (L1-resident).
__device__ __forceinline__ float dot_row(const float* __restrict__ W, int row,
                                         const float4 h[4], int lane) {
    const float4* w4 = reinterpret_cast<const float4*>(W) + (size_t)row * (HH / 4);
    float s = 0.f;
#pragma unroll
    for (int j = 0; j < 4; j++) {
        float4 w = __ldg(&w4[lane + 32 * j]);
        s = fmaf(w.x, h[j].x, s);
        s = fmaf(w.y, h[j].y, s);
        s = fmaf(w.z, h[j].z, s);
        s = fmaf(w.w, h[j].w, s);
    }
    return warp_sum(s);
}

__device__ __forceinline__ float sigf(float x) { return 1.f / (1.f + __expf(-x)); }

// ---- main persistent kernel --------------------------------------------------
__global__ void __launch_bounds__(TPB, 1) lstm_main_kernel(
    const float* __restrict__ input,
    const float* __restrict__ Wih1, const float* __restrict__ Whh1,
    const float* __restrict__ bih1, const float* __restrict__ bhh1,
    const float* __restrict__ Wih2, const float* __restrict__ Whh2,
    const float* __restrict__ bih2, const float* __restrict__ bhh2,
    const float* __restrict__ Wlin, const float* __restrict__ blin,
    float* __restrict__ out)
{
    const int lane = threadIdx.x & 31;
    const int gw   = blockIdx.x * (TPB / 32) + (threadIdx.x >> 5);  // 0..1023
    unsigned ep = 0u;
    const float blin0 = __ldg(blin);

    for (int t = 0; t <= NSTEP; ++t) {   // t == NSTEP is the output epilogue only
        const float* h1in  = g_h1[t & 1];
        const float* h2in  = g_h2[t & 1];
        float*       h1out = g_h1[(t + 1) & 1];
        float*       h2out = g_h2[(t + 1) & 1];

        // ---- x for this step (encode: input; AR: y = Wlin . h2 + blin) ----
        float x = 0.f;
        if (gw < HH) {
            if (t < T_ENC) {
                x = __ldg(&input[255 * T_ENC + t]);
            } else {
                // h2in is h2 after step t-1 (published through the last barrier).
                float4 h2r[4];
                load_h_cg(h2in, h2r, lane);
                float y = dot_row(Wlin, 0, h2r, lane) + blin0;
                if (gw == 0 && lane == 0) out[t - T_ENC] = y;  // out[0..63]
                x = y;  // identical (bitwise) in every warp: same data, same order
            }
        }
        if (t == NSTEP) break;  // final output written; all CTAs exit uniformly

        // ---------------- Phase A ----------------
        if (gw < HH) {
            // layer-1 element k: rows k, k+512, k+1024, k+1536 of Whh1
            const int k = gw;
            float4 hr[4];
            load_h_cg(h1in, hr, lane);
            float si = dot_row(Whh1, k,          hr, lane);
            float sf = dot_row(Whh1, k + 512,    hr, lane);
            float sg = dot_row(Whh1, k + 1024,   hr, lane);
            float so = dot_row(Whh1, k + 1536,   hr, lane);
            if (lane == 0) {
                float pi = si + __ldg(&bih1[k])        + __ldg(&bhh1[k])        + __ldg(&Wih1[k])        * x;
                float pf = sf + __ldg(&bih1[k + 512])  + __ldg(&bhh1[k + 512])  + __ldg(&Wih1[k + 512])  * x;
                float pg = sg + __ldg(&bih1[k + 1024]) + __ldg(&bhh1[k + 1024]) + __ldg(&Wih1[k + 1024]) * x;
                float po = so + __ldg(&bih1[k + 1536]) + __ldg(&bhh1[k + 1536]) + __ldg(&Wih1[k + 1536]) * x;
                float i_ = sigf(pi), f_ = sigf(pf), g_ = tanhf(pg), o_ = sigf(po);
                float c = f_ * g_c1[k] + i_ * g_;   // c1 owned by this warp: in-place
                g_c1[k] = c;
                __stcg(&h1out[k], o_ * tanhf(c));
            }
        } else {
            // layer-2 recurrent part for element k: Whh2 rows @ h2_old + biases
            const int k = gw - HH;
            float4 hr[4];
            load_h_cg(h2in, hr, lane);
            float si = dot_row(Whh2, k,          hr, lane);
            float sf = dot_row(Whh2, k + 512,    hr, lane);
            float sg = dot_row(Whh2, k + 1024,   hr, lane);
            float so = dot_row(Whh2, k + 1536,   hr, lane);
            if (lane == 0) {
                __stcg(&g_part2[k],        si + __ldg(&bih2[k])        + __ldg(&bhh2[k]));
                __stcg(&g_part2[k + 512],  sf + __ldg(&bih2[k + 512])  + __ldg(&bhh2[k + 512]));
                __stcg(&g_part2[k + 1024], sg + __ldg(&bih2[k + 1024]) + __ldg(&bhh2[k + 1024]));
                __stcg(&g_part2[k + 1536], so + __ldg(&bih2[k + 1536]) + __ldg(&bhh2[k + 1536]));
            }
        }
        grid_sync(ep);

        // ---------------- Phase B ----------------
        if (gw < HH) {
            const int k = gw;
            float4 hr[4];
            load_h_cg(h1out, hr, lane);   // h1_new, published by phase A barrier
            float si = dot_row(Wih2, k,          hr, lane);
            float sf = dot_row(Wih2, k + 512,    hr, lane);
            float sg = dot_row(Wih2, k + 1024,   hr, lane);
            float so = dot_row(Wih2, k + 1536,   hr, lane);
            if (lane == 0) {
                float pi = si + __ldcg(&g_part2[k]);
                float pf = sf + __ldcg(&g_part2[k + 512]);
                float pg = sg + __ldcg(&g_part2[k + 1024]);
                float po = so + __ldcg(&g_part2[k + 1536]);
                float i_ = sigf(pi), f_ = sigf(pf), g_ = tanhf(pg), o_ = sigf(po);
                float c = f_ * g_c2[k] + i_ * g_;   // c2 owned by this warp: in-place
                g_c2[k] = c;
                __stcg(&h2out[k], o_ * tanhf(c));
            }
        }
        grid_sync(ep);
    }
}

// ---------------------------------------------------------------------------
// inputs (metadata order): 0 input(256x1024 f32), 1 pred_len(i32, =64),
// 2 Wih1(2048x1), 3 Whh1(2048x512), 4 bih1(2048), 5 bhh1(2048),
// 6 Wih2(2048x512), 7 Whh2(2048x512), 8 bih2(2048), 9 bhh2(2048),
// 10 Wlin(1x512), 11 blin(1).  output: 64 f32.
// ---------------------------------------------------------------------------
extern "C" void kernel_launch(void* const* d_in, const int* in_sizes, int n_in,
                              void* d_out, int out_size) {
    (void)in_sizes; (void)n_in; (void)out_size;
    const float* input = (const float*)d_in[0];
    const float* Wih1  = (const float*)d_in[2];
    const float* Whh1  = (const float*)d_in[3];
    const float* bih1  = (const float*)d_in[4];
    const float* bhh1  = (const float*)d_in[5];
    const float* Wih2  = (const float*)d_in[6];
    const float* Whh2  = (const float*)d_in[7];
    const float* bih2  = (const float*)d_in[8];
    const float* bhh2  = (const float*)d_in[9];
    const float* Wlin  = (const float*)d_in[10];
    const float* blin  = (const float*)d_in[11];

    lstm_init_kernel<<<1, 256>>>();
    lstm_main_kernel<<<GRID, TPB>>>(input, Wih1, Whh1, bih1, bhh1,
                                    Wih2, Whh2, bih2, bhh2,
                                    Wlin, blin, (float*)d_out);
}

// round 6
// speedup vs baseline: 1.1906x; 1.1906x over previous
#include <cuda_runtime.h>

// ---------------------------------------------------------------------------
// 2-layer LSTM (H=512) encode (T=1024) + AR decode (64 outputs), batch row 255
// only (reference output depends only on that row).
//
// Persistent kernel: 128 CTAs x 256 threads = 1024 warps.
//   Phase A: warps   0..511  -> layer-1 gates (reg-resident Whh1 rows)
//            warps 512..1023 -> layer-2 recurrent part (reg-resident Whh2 rows)
//   grid barrier
//   Phase B: warps   0..511  -> layer-2 gates (reg-resident Wih2 rows + part2)
//   grid barrier
//
// KEY CHANGE vs previous round: ALL weights live in REGISTERS (64-128 regs per
// thread), because the grid barrier's gpu-scope acquire flushes L1D (CCTL.IVALL)
// every phase — any L1-cached weight would be re-fetched from DRAM each step
// (measured: 1736 GB/s of pure weight re-fetch traffic). Cell state c1/c2 and
// bias sums are also register-resident. Only the h vectors and the 8KB gate
// partial exchange go through memory, via .cg (L2).
// ---------------------------------------------------------------------------

#define GRID   128
#define TPB    256
#define HH     512
#define T_ENC  1024
#define PRED   64
#define NSTEP  (T_ENC + PRED - 1)   // 1087 LSTM steps

// ---- persistent device state (reset by init kernel every launch) -----------
__device__ __align__(16) float g_h1[2][HH];
__device__ __align__(16) float g_h2[2][HH];
__device__ __align__(16) float g_part2[4 * HH];
__device__ unsigned g_count;
__device__ unsigned g_epoch;

__global__ void lstm_init_kernel() {
    int i = threadIdx.x;
    for (int j = i; j < HH; j += blockDim.x) {
        g_h1[0][j] = 0.f; g_h1[1][j] = 0.f;
        g_h2[0][j] = 0.f; g_h2[1][j] = 0.f;
    }
    if (i == 0) { g_count = 0u; g_epoch = 0u; }
}

// ---- acquire/release primitives ---------------------------------------------
__device__ __forceinline__ unsigned atom_add_acqrel(unsigned* p, unsigned v) {
    unsigned old;
    asm volatile("atom.acq_rel.gpu.add.u32 %0, [%1], %2;"
                 : "=r"(old) : "l"(p), "r"(v) : "memory");
    return old;
}
__device__ __forceinline__ void st_release(unsigned* p, unsigned v) {
    asm volatile("st.release.gpu.u32 [%0], %1;" :: "l"(p), "r"(v) : "memory");
}
__device__ __forceinline__ unsigned ld_acquire(unsigned* p) {
    unsigned v;
    asm volatile("ld.acquire.gpu.u32 %0, [%1];" : "=r"(v) : "l"(p) : "memory");
    return v;
}

// Grid-wide barrier (monotonic epoch; init kernel resets per launch).
__device__ __forceinline__ void grid_sync(unsigned& ep) {
    __syncthreads();
    if (threadIdx.x == 0) {
        ep += 1u;
        unsigned prev = atom_add_acqrel(&g_count, 1u);
        if (prev == ep * GRID - 1u) {
            st_release(&g_epoch, ep);
        } else {
            while (ld_acquire(&g_epoch) < ep) { }
        }
    }
    __syncthreads();
}

// ---- math helpers ------------------------------------------------------------
__device__ __forceinline__ float warp_sum(float s) {
#pragma unroll
    for (int o = 16; o; o >>= 1) s += __shfl_xor_sync(0xffffffffu, s, o);
    return s;
}

// Load h (512 floats) as 4 float4 per lane from L2 (.cg: mutable, cross-SM).
__device__ __forceinline__ void load_h_cg(const float* buf, float4 h[4], int lane) {
    const float4* b4 = reinterpret_cast<const float4*>(buf);
#pragma unroll
    for (int j = 0; j < 4; j++) h[j] = __ldcg(&b4[lane + 32 * j]);
}

// 4 register-weight row-dots against h, with interleaved 4-way butterfly reduce.
// Same accumulation order as the previous (verified) version -> bitwise identical.
__device__ __forceinline__ void mv4(const float4 w[4][4], const float4 h[4], float s[4]) {
#pragma unroll
    for (int g = 0; g < 4; ++g) {
        float a = 0.f;
#pragma unroll
        for (int j = 0; j < 4; ++j) {
            a = fmaf(w[g][j].x, h[j].x, a);
            a = fmaf(w[g][j].y, h[j].y, a);
            a = fmaf(w[g][j].z, h[j].z, a);
            a = fmaf(w[g][j].w, h[j].w, a);
        }
        s[g] = a;
    }
#pragma unroll
    for (int o = 16; o; o >>= 1) {
#pragma unroll
        for (int g = 0; g < 4; ++g) s[g] += __shfl_xor_sync(0xffffffffu, s[g], o);
    }
}

__device__ __forceinline__ float sigf(float x) { return 1.f / (1.f + __expf(-x)); }

// ---- main persistent kernel ----------------------------------------------------
__global__ void __launch_bounds__(TPB, 1) lstm_main_kernel(
    const float* __restrict__ input,
    const float* __restrict__ Wih1, const float* __restrict__ Whh1,
    const float* __restrict__ bih1, const float* __restrict__ bhh1,
    const float* __restrict__ Wih2, const float* __restrict__ Whh2,
    const float* __restrict__ bih2, const float* __restrict__ bhh2,
    const float* __restrict__ Wlin, const float* __restrict__ blin,
    float* __restrict__ out)
{
    const int  lane = threadIdx.x & 31;
    const int  gw   = blockIdx.x * (TPB / 32) + (threadIdx.x >> 5);  // 0..1023
    const bool is1  = (gw < HH);
    const int  k    = is1 ? gw : gw - HH;

    // ---- one-time: load this warp's weight rows into REGISTERS ----
    // Phase-A matrix: Whh1 (type-1 warps) or Whh2 (type-2 warps), rows k+512g.
    float4 wA[4][4];
    {
        const float4* WA = reinterpret_cast<const float4*>(is1 ? Whh1 : Whh2);
#pragma unroll
        for (int g = 0; g < 4; ++g) {
            const float4* row = WA + (size_t)(k + 512 * g) * (HH / 4);
#pragma unroll
            for (int j = 0; j < 4; ++j) wA[g][j] = __ldg(&row[lane + 32 * j]);
        }
    }
    // Phase-B matrix: Wih2 (type-1 warps only).
    float4 wB[4][4];
    if (is1) {
        const float4* WB = reinterpret_cast<const float4*>(Wih2);
#pragma unroll
        for (int g = 0; g < 4; ++g) {
            const float4* row = WB + (size_t)(k + 512 * g) * (HH / 4);
#pragma unroll
            for (int j = 0; j < 4; ++j) wB[g][j] = __ldg(&row[lane + 32 * j]);
        }
    } else {
#pragma unroll
        for (int g = 0; g < 4; ++g)
#pragma unroll
            for (int j = 0; j < 4; ++j) wB[g][j] = make_float4(0.f, 0.f, 0.f, 0.f);
    }
    // Wlin row (for AR decode), bias sums, Wih1 column — all register-resident.
    float4 wlin4[4];
    {
        const float4* WL = reinterpret_cast<const float4*>(Wlin);
#pragma unroll
        for (int j = 0; j < 4; ++j) wlin4[j] = __ldg(&WL[lane + 32 * j]);
    }
    float bsum[4], wx[4];
#pragma unroll
    for (int g = 0; g < 4; ++g) {
        int r = k + 512 * g;
        if (is1) { bsum[g] = __ldg(&bih1[r]) + __ldg(&bhh1[r]); wx[g] = __ldg(&Wih1[r]); }
        else     { bsum[g] = __ldg(&bih2[r]) + __ldg(&bhh2[r]); wx[g] = 0.f; }
    }
    const float blin0 = __ldg(blin);

    float c1s = 0.f, c2s = 0.f;   // cell state, owned by lane 0 of this warp
    unsigned ep = 0u;

    for (int t = 0; t <= NSTEP; ++t) {   // t == NSTEP: output epilogue only
        const float* h1in  = g_h1[t & 1];
        const float* h2in  = g_h2[t & 1];
        float*       h1out = g_h1[(t + 1) & 1];
        float*       h2out = g_h2[(t + 1) & 1];

        // ---- x for this step (encode: input; AR: y = Wlin . h2 + blin) ----
        float x = 0.f;
        if (is1) {
            if (t < T_ENC) {
                x = __ldg(&input[255 * T_ENC + t]);
            } else {
                float4 h2r[4];
                load_h_cg(h2in, h2r, lane);
                float y = 0.f;
#pragma unroll
                for (int j = 0; j < 4; ++j) {
                    y = fmaf(wlin4[j].x, h2r[j].x, y);
                    y = fmaf(wlin4[j].y, h2r[j].y, y);
                    y = fmaf(wlin4[j].z, h2r[j].z, y);
                    y = fmaf(wlin4[j].w, h2r[j].w, y);
                }
                y = warp_sum(y) + blin0;
                if (gw == 0 && lane == 0) out[t - T_ENC] = y;
                x = y;  // bitwise identical in every warp (same data, same order)
            }
        }
        if (t == NSTEP) break;

        // ---------------- Phase A ----------------
        if (is1) {
            float4 hr[4];
            load_h_cg(h1in, hr, lane);
            float s[4];
            mv4(wA, hr, s);
            if (lane == 0) {
                float pi = s[0] + bsum[0] + wx[0] * x;
                float pf = s[1] + bsum[1] + wx[1] * x;
                float pg = s[2] + bsum[2] + wx[2] * x;
                float po = s[3] + bsum[3] + wx[3] * x;
                float i_ = sigf(pi), f_ = sigf(pf), g_ = tanhf(pg), o_ = sigf(po);
                c1s = f_ * c1s + i_ * g_;
                __stcg(&h1out[k], o_ * tanhf(c1s));
            }
        } else {
            float4 hr[4];
            load_h_cg(h2in, hr, lane);
            float s[4];
            mv4(wA, hr, s);
            if (lane == 0) {
#pragma unroll
                for (int g = 0; g < 4; ++g)
                    __stcg(&g_part2[k + 512 * g], s[g] + bsum[g]);
            }
        }
        grid_sync(ep);

        // ---------------- Phase B ----------------
        if (is1) {
            float4 hr[4];
            load_h_cg(h1out, hr, lane);    // h1_new, published by phase-A barrier
            float s[4];
            mv4(wB, hr, s);
            if (lane == 0) {
                float pi = s[0] + __ldcg(&g_part2[k]);
                float pf = s[1] + __ldcg(&g_part2[k + 512]);
                float pg = s[2] + __ldcg(&g_part2[k + 1024]);
                float po = s[3] + __ldcg(&g_part2[k + 1536]);
                float i_ = sigf(pi), f_ = sigf(pf), g_ = tanhf(pg), o_ = sigf(po);
                c2s = f_ * c2s + i_ * g_;
                __stcg(&h2out[k], o_ * tanhf(c2s));
            }
        }
        grid_sync(ep);
    }
}

// ---------------------------------------------------------------------------
// inputs (metadata order): 0 input(256x1024 f32), 1 pred_len(i32, =64),
// 2 Wih1(2048x1), 3 Whh1(2048x512), 4 bih1(2048), 5 bhh1(2048),
// 6 Wih2(2048x512), 7 Whh2(2048x512), 8 bih2(2048), 9 bhh2(2048),
// 10 Wlin(1x512), 11 blin(1).  output: 64 f32.
// ---------------------------------------------------------------------------
extern "C" void kernel_launch(void* const* d_in, const int* in_sizes, int n_in,
                              void* d_out, int out_size) {
    (void)in_sizes; (void)n_in; (void)out_size;
    const float* input = (const float*)d_in[0];
    const float* Wih1  = (const float*)d_in[2];
    const float* Whh1  = (const float*)d_in[3];
    const float* bih1  = (const float*)d_in[4];
    const float* bhh1  = (const float*)d_in[5];
    const float* Wih2  = (const float*)d_in[6];
    const float* Whh2  = (const float*)d_in[7];
    const float* bih2  = (const float*)d_in[8];
    const float* bhh2  = (const float*)d_in[9];
    const float* Wlin  = (const float*)d_in[10];
    const float* blin  = (const float*)d_in[11];

    lstm_init_kernel<<<1, 256>>>();
    lstm_main_kernel<<<GRID, TPB>>>(input, Wih1, Whh1, bih1, bhh1,
                                    Wih2, Whh2, bih2, bhh2,
                                    Wlin, blin, (float*)d_out);
}

// round 8
// speedup vs baseline: 1.5202x; 1.2768x over previous
#include <cuda_runtime.h>

// ---------------------------------------------------------------------------
// 2-layer LSTM (H=512) encode (T=1024) + AR decode (64 outputs), batch row 255
// only (reference output depends only on that row).
//
// Persistent kernel, 128 CTAs x 256 threads = 1024 warps:
//   type-1 warps (gw 0..511):   layer-1 cell; hold Whh1 rows + Wlin in regs
//   type-2 warps (gw 512..1023): layer-2 cell; hold Whh2 AND Wih2 rows in regs
//
// ENCODE is software-pipelined (layer-2 lags layer-1 by one step):
//   interval t: type-1 computes h1[t], type-2 computes h2[t-1]  -> ONE barrier.
// AR decode is sequential (y feedback): two phases/step, but type-2 keeps its
// Whh2 partial sums in registers across the barrier (no g_part2 exchange).
//
// Grid barrier: atomic arrival counter + LAST-ARRIVER BROADCAST to 128
// per-CTA flag words on distinct 128B lines; each CTA polls only its own line
// (no hot-line contention). Monotonic epochs; init kernel resets per launch.
// ---------------------------------------------------------------------------

#define GRID   128
#define TPB    256
#define HH     512
#define T_ENC  1024
#define PRED   64

// ---- persistent device state (reset by init kernel every launch) -----------
__device__ __align__(16) float g_h1[2][HH];
__device__ __align__(16) float g_h2[2][HH];
__device__ unsigned g_count;
__device__ __align__(128) unsigned g_flag[GRID * 32];   // one 128B line per CTA

__global__ void lstm_init_kernel() {
    int i = threadIdx.x;
    for (int j = i; j < HH; j += blockDim.x) {
        g_h1[0][j] = 0.f; g_h1[1][j] = 0.f;
        g_h2[0][j] = 0.f; g_h2[1][j] = 0.f;
    }
    for (int j = i; j < GRID * 32; j += blockDim.x) g_flag[j] = 0u;
    if (i == 0) g_count = 0u;
}

// ---- acquire/release primitives ---------------------------------------------
__device__ __forceinline__ unsigned atom_add_acqrel(unsigned* p, unsigned v) {
    unsigned old;
    asm volatile("atom.acq_rel.gpu.add.u32 %0, [%1], %2;"
                 : "=r"(old) : "l"(p), "r"(v) : "memory");
    return old;
}
__device__ __forceinline__ void st_release(unsigned* p, unsigned v) {
    asm volatile("st.release.gpu.u32 [%0], %1;" :: "l"(p), "r"(v) : "memory");
}
__device__ __forceinline__ unsigned ld_acquire(unsigned* p) {
    unsigned v;
    asm volatile("ld.acquire.gpu.u32 %0, [%1];" : "=r"(v) : "l"(p) : "memory");
    return v;
}

// Grid barrier: arrive on shared counter; last arriver's warp broadcasts the
// epoch to per-CTA flags (release); each CTA leader polls its OWN flag line.
__device__ __forceinline__ void grid_sync(unsigned& ep, int bid) {
    __syncthreads();
    if (threadIdx.x < 32) {
        ep += 1u;
        unsigned prev = 0u;
        if (threadIdx.x == 0) prev = atom_add_acqrel(&g_count, 1u);
        prev = __shfl_sync(0xffffffffu, prev, 0);
        if (prev == ep * GRID - 1u) {
            __syncwarp();   // order lanes after lane0's acquiring atomic
#pragma unroll
            for (int i = threadIdx.x; i < GRID; i += 32)
                st_release(&g_flag[i * 32], ep);
        } else if (threadIdx.x == 0) {
            while (ld_acquire(&g_flag[bid * 32]) < ep) { }
        }
    }
    __syncthreads();
}

// ---- math helpers ------------------------------------------------------------
__device__ __forceinline__ float warp_sum(float s) {
#pragma unroll
    for (int o = 16; o; o >>= 1) s += __shfl_xor_sync(0xffffffffu, s, o);
    return s;
}

__device__ __forceinline__ void load_h_cg(const float* buf, float4 h[4], int lane) {
    const float4* b4 = reinterpret_cast<const float4*>(buf);
#pragma unroll
    for (int j = 0; j < 4; j++) h[j] = __ldcg(&b4[lane + 32 * j]);
}

// 4 register-weight row-dots vs h, interleaved butterfly allreduce.
__device__ __forceinline__ void mv4(const float4 w[4][4], const float4 h[4], float s[4]) {
#pragma unroll
    for (int g = 0; g < 4; ++g) {
        float a = 0.f;
#pragma unroll
        for (int j = 0; j < 4; ++j) {
            a = fmaf(w[g][j].x, h[j].x, a);
            a = fmaf(w[g][j].y, h[j].y, a);
            a = fmaf(w[g][j].z, h[j].z, a);
            a = fmaf(w[g][j].w, h[j].w, a);
        }
        s[g] = a;
    }
#pragma unroll
    for (int o = 16; o; o >>= 1)
#pragma unroll
        for (int g = 0; g < 4; ++g) s[g] += __shfl_xor_sync(0xffffffffu, s[g], o);
}

// 8 dots (two matrices x 4 gates), interleaved butterfly allreduce.
__device__ __forceinline__ void mv8(const float4 wa[4][4], const float4 ha[4],
                                    const float4 wb[4][4], const float4 hb[4],
                                    float s[8]) {
#pragma unroll
    for (int g = 0; g < 4; ++g) {
        float a = 0.f, b = 0.f;
#pragma unroll
        for (int j = 0; j < 4; ++j) {
            a = fmaf(wa[g][j].x, ha[j].x, a);
            a = fmaf(wa[g][j].y, ha[j].y, a);
            a = fmaf(wa[g][j].z, ha[j].z, a);
            a = fmaf(wa[g][j].w, ha[j].w, a);
            b = fmaf(wb[g][j].x, hb[j].x, b);
            b = fmaf(wb[g][j].y, hb[j].y, b);
            b = fmaf(wb[g][j].z, hb[j].z, b);
            b = fmaf(wb[g][j].w, hb[j].w, b);
        }
        s[g] = a; s[4 + g] = b;
    }
#pragma unroll
    for (int o = 16; o; o >>= 1)
#pragma unroll
        for (int g = 0; g < 8; ++g) s[g] += __shfl_xor_sync(0xffffffffu, s[g], o);
}

__device__ __forceinline__ float sigf(float x) { return 1.f / (1.f + __expf(-x)); }

__device__ __forceinline__ float cellf(float pi, float pf, float pg, float po, float& c) {
    float i_ = sigf(pi), f_ = sigf(pf), g_ = tanhf(pg), o_ = sigf(po);
    c = f_ * c + i_ * g_;
    return o_ * tanhf(c);
}

// ---- main persistent kernel ----------------------------------------------------
__global__ void __launch_bounds__(TPB, 1) lstm_main_kernel(
    const float* __restrict__ input,
    const float* __restrict__ Wih1, const float* __restrict__ Whh1,
    const float* __restrict__ bih1, const float* __restrict__ bhh1,
    const float* __restrict__ Wih2, const float* __restrict__ Whh2,
    const float* __restrict__ bih2, const float* __restrict__ bhh2,
    const float* __restrict__ Wlin, const float* __restrict__ blin,
    float* __restrict__ out)
{
    const int  lane = threadIdx.x & 31;
    const int  bid  = blockIdx.x;
    const int  gw   = bid * (TPB / 32) + (threadIdx.x >> 5);  // 0..1023
    const bool is1  = (gw < HH);
    const int  k    = is1 ? gw : gw - HH;

    // ---- one-time: this warp's weight rows -> REGISTERS ----
    // type-1: wA = Whh1 rows {k+512g}; type-2: wA = Whh2 rows, wB = Wih2 rows.
    float4 wA[4][4], wB[4][4];
    {
        const float4* WA = reinterpret_cast<const float4*>(is1 ? Whh1 : Whh2);
#pragma unroll
        for (int g = 0; g < 4; ++g) {
            const float4* row = WA + (size_t)(k + 512 * g) * (HH / 4);
#pragma unroll
            for (int j = 0; j < 4; ++j) wA[g][j] = __ldg(&row[lane + 32 * j]);
        }
        if (!is1) {
            const float4* WB = reinterpret_cast<const float4*>(Wih2);
#pragma unroll
            for (int g = 0; g < 4; ++g) {
                const float4* row = WB + (size_t)(k + 512 * g) * (HH / 4);
#pragma unroll
                for (int j = 0; j < 4; ++j) wB[g][j] = __ldg(&row[lane + 32 * j]);
            }
        } else {
#pragma unroll
            for (int g = 0; g < 4; ++g)
#pragma unroll
                for (int j = 0; j < 4; ++j) wB[g][j] = make_float4(0.f, 0.f, 0.f, 0.f);
        }
    }
    float4 wlin4[4];
    {
        const float4* WL = reinterpret_cast<const float4*>(Wlin);
#pragma unroll
        for (int j = 0; j < 4; ++j) wlin4[j] = __ldg(&WL[lane + 32 * j]);
    }
    float bsum[4], wx[4];
#pragma unroll
    for (int g = 0; g < 4; ++g) {
        int r = k + 512 * g;
        if (is1) { bsum[g] = __ldg(&bih1[r]) + __ldg(&bhh1[r]); wx[g] = __ldg(&Wih1[r]); }
        else     { bsum[g] = __ldg(&bih2[r]) + __ldg(&bhh2[r]); wx[g] = 0.f; }
    }
    const float blin0 = __ldg(blin);

    float cs = 0.f;          // c1 (type-1) or c2 (type-2), lane 0 of this warp
    unsigned ep = 0u;

    // ================= ENCODE: pipelined, ONE barrier per step =================
    // interval t: type-1 computes h1[t]; type-2 computes h2[t-1].
    // h1[s] lives in g_h1[(s+1)&1]; h2[s] lives in g_h2[(s+1)&1].
    for (int t = 0; t < T_ENC; ++t) {
        if (is1) {
            float x = __ldg(&input[255 * T_ENC + t]);
            float4 hr[4];
            load_h_cg(g_h1[t & 1], hr, lane);              // h1[t-1]
            float s[4];
            mv4(wA, hr, s);
            if (lane == 0) {
                float h = cellf(s[0] + bsum[0] + wx[0] * x,
                                s[1] + bsum[1] + wx[1] * x,
                                s[2] + bsum[2] + wx[2] * x,
                                s[3] + bsum[3] + wx[3] * x, cs);
                __stcg(&g_h1[(t + 1) & 1][k], h);          // h1[t]
            }
        } else if (t >= 1) {
            float4 h1r[4], h2r[4];
            load_h_cg(g_h1[t & 1], h1r, lane);             // h1[t-1]
            load_h_cg(g_h2[(t - 1) & 1], h2r, lane);       // h2[t-2]
            float s[8];
            mv8(wA, h2r, wB, h1r, s);                      // Whh2 dots, Wih2 dots
            if (lane == 0) {
                float h = cellf(s[0] + s[4] + bsum[0],
                                s[1] + s[5] + bsum[1],
                                s[2] + s[6] + bsum[2],
                                s[3] + s[7] + bsum[3], cs);
                __stcg(&g_h2[t & 1][k], h);                // h2[t-1]
            }
        }
        grid_sync(ep, bid);
    }

    // ================= DRAIN: compute h2[1023] =================
    if (!is1) {
        float4 h1r[4], h2r[4];
        load_h_cg(g_h1[T_ENC & 1], h1r, lane);             // h1[1023]
        load_h_cg(g_h2[(T_ENC - 1) & 1], h2r, lane);       // h2[1022]
        float s[8];
        mv8(wA, h2r, wB, h1r, s);
        if (lane == 0) {
            float h = cellf(s[0] + s[4] + bsum[0],
                            s[1] + s[5] + bsum[1],
                            s[2] + s[6] + bsum[2],
                            s[3] + s[7] + bsum[3], cs);
            __stcg(&g_h2[T_ENC & 1][k], h);                // h2[1023]
        }
    }
    grid_sync(ep, bid);

    // ================= AR DECODE: t = 1024 .. 1086, two barriers/step ==========
    for (int t = T_ENC; t < T_ENC + PRED - 1; ++t) {
        float sA[4];
        if (is1) {
            // y(t-1) = Wlin . h2[t-1] + blin  (h2[t-1] in g_h2[t&1])
            float4 h2r[4];
            load_h_cg(g_h2[t & 1], h2r, lane);
            float y = 0.f;
#pragma unroll
            for (int j = 0; j < 4; ++j) {
                y = fmaf(wlin4[j].x, h2r[j].x, y);
                y = fmaf(wlin4[j].y, h2r[j].y, y);
                y = fmaf(wlin4[j].z, h2r[j].z, y);
                y = fmaf(wlin4[j].w, h2r[j].w, y);
            }
            y = warp_sum(y) + blin0;
            if (gw == 0 && lane == 0) out[t - T_ENC] = y;  // out[0..62]
            float x = y;   // bitwise identical in all warps
            float4 hr[4];
            load_h_cg(g_h1[t & 1], hr, lane);              // h1[t-1]
            float s[4];
            mv4(wA, hr, s);
            if (lane == 0) {
                float h = cellf(s[0] + bsum[0] + wx[0] * x,
                                s[1] + bsum[1] + wx[1] * x,
                                s[2] + bsum[2] + wx[2] * x,
                                s[3] + bsum[3] + wx[3] * x, cs);
                __stcg(&g_h1[(t + 1) & 1][k], h);          // h1[t]
            }
        } else {
            float4 h2r[4];
            load_h_cg(g_h2[t & 1], h2r, lane);             // h2[t-1]
            mv4(wA, h2r, sA);                              // Whh2 partials, kept in regs
        }
        grid_sync(ep, bid);

        if (!is1) {
            float4 h1r[4];
            load_h_cg(g_h1[(t + 1) & 1], h1r, lane);       // h1[t]
            float s[4];
            mv4(wB, h1r, s);
            if (lane == 0) {
                float h = cellf(sA[0] + s[0] + bsum[0],
                                sA[1] + s[1] + bsum[1],
                                sA[2] + s[2] + bsum[2],
                                sA[3] + s[3] + bsum[3], cs);
                __stcg(&g_h2[(t + 1) & 1][k], h);          // h2[t]
            }
        }
        grid_sync(ep, bid);
    }

    // ================= EPILOGUE: out[63] = Wlin . h2[1086] + blin ==============
    if (gw == 0) {
        float4 h2r[4];
        load_h_cg(g_h2[(T_ENC + PRED - 1) & 1], h2r, lane); // h2[1086] (parity: (1086+1)&1 = 1)
        float y = 0.f;
#pragma unroll
        for (int j = 0; j < 4; ++j) {
            y = fmaf(wlin4[j].x, h2r[j].x, y);
            y = fmaf(wlin4[j].y, h2r[j].y, y);
            y = fmaf(wlin4[j].z, h2r[j].z, y);
            y = fmaf(wlin4[j].w, h2r[j].w, y);
        }
        y = warp_sum(y) + blin0;
        if (lane == 0) out[PRED - 1] = y;
    }
}

// ---------------------------------------------------------------------------
// inputs (metadata order): 0 input(256x1024 f32), 1 pred_len(i32, =64),
// 2 Wih1(2048x1), 3 Whh1(2048x512), 4 bih1(2048), 5 bhh1(2048),
// 6 Wih2(2048x512), 7 Whh2(2048x512), 8 bih2(2048), 9 bhh2(2048),
// 10 Wlin(1x512), 11 blin(1).  output: 64 f32.
// ---------------------------------------------------------------------------
extern "C" void kernel_launch(void* const* d_in, const int* in_sizes, int n_in,
                              void* d_out, int out_size) {
    (void)in_sizes; (void)n_in; (void)out_size;
    const float* input = (const float*)d_in[0];
    const float* Wih1  = (const float*)d_in[2];
    const float* Whh1  = (const float*)d_in[3];
    const float* bih1  = (const float*)d_in[4];
    const float* bhh1  = (const float*)d_in[5];
    const float* Wih2  = (const float*)d_in[6];
    const float* Whh2  = (const float*)d_in[7];
    const float* bih2  = (const float*)d_in[8];
    const float* bhh2  = (const float*)d_in[9];
    const float* Wlin  = (const float*)d_in[10];
    const float* blin  = (const float*)d_in[11];

    lstm_init_kernel<<<1, 256>>>();
    lstm_main_kernel<<<GRID, TPB>>>(input, Wih1, Whh1, bih1, bhh1,
                                    Wih2, Whh2, bih2, bhh2,
                                    Wlin, blin, (float*)d_out);
}

// round 9
// speedup vs baseline: 1.6967x; 1.1161x over previous
#include <cuda_runtime.h>

// ---------------------------------------------------------------------------
// 2-layer LSTM (H=512) encode (T=1024) + AR decode (64 outputs), batch row 255
// only (reference output depends only on that row).
//
// Persistent kernel, 128 CTAs x 256 threads = 1024 warps:
//   type-1 warps (gw 0..511):   layer-1 cell; hold Whh1 rows + Wlin in regs
//   type-2 warps (gw 512..1023): layer-2 cell; hold Whh2 AND Wih2 rows in regs
//
// ENCODE pipelined (layer-2 lags by one step): ONE barrier per encode step.
// AR decode: two barriers/step (y feedback is sequential).
//
// Grid barrier (NEW): no atomics. Each CTA leader st.release's its monotonic
// epoch into its own 128B-aligned slot; every CTA's warp 0 polls ALL 128 slots
// (4 ld.acquire per lane + __all_sync vote). No same-address atomic convoy
// (was ~3.5K cyc for 128 acq_rel atomics), no master->flag broadcast hops.
// ---------------------------------------------------------------------------

#define GRID   128
#define TPB    256
#define HH     512
#define T_ENC  1024
#define PRED   64

// ---- persistent device state (reset by init kernel every launch) -----------
__device__ __align__(16) float g_h1[2][HH];
__device__ __align__(16) float g_h2[2][HH];
__device__ __align__(128) unsigned g_arrive[GRID * 32];  // one 128B line per CTA

__global__ void lstm_init_kernel() {
    int i = threadIdx.x;
    for (int j = i; j < HH; j += blockDim.x) {
        g_h1[0][j] = 0.f; g_h1[1][j] = 0.f;
        g_h2[0][j] = 0.f; g_h2[1][j] = 0.f;
    }
    for (int j = i; j < GRID * 32; j += blockDim.x) g_arrive[j] = 0u;
}

// ---- acquire/release primitives ---------------------------------------------
__device__ __forceinline__ void st_release(unsigned* p, unsigned v) {
    asm volatile("st.release.gpu.u32 [%0], %1;" :: "l"(p), "r"(v) : "memory");
}
__device__ __forceinline__ unsigned ld_acquire(unsigned* p) {
    unsigned v;
    asm volatile("ld.acquire.gpu.u32 %0, [%1];" : "=r"(v) : "l"(p) : "memory");
    return v;
}

// Decentralized grid barrier: CTA leader releases its epoch slot; warp 0 of
// EVERY CTA polls all GRID slots until all have reached the epoch.
// Monotonic epochs (>=): no reset race; init kernel zeroes per launch.
__device__ __forceinline__ void grid_sync(unsigned& ep, int bid) {
    __syncthreads();                       // all CTA stores done before release
    if (threadIdx.x < 32) {
        ep += 1u;
        if (threadIdx.x == 0) st_release(&g_arrive[bid * 32], ep);
        const int l = threadIdx.x;
        bool ok;
        do {
            unsigned v0 = ld_acquire(&g_arrive[(l      ) * 32]);
            unsigned v1 = ld_acquire(&g_arrive[(l +  32) * 32]);
            unsigned v2 = ld_acquire(&g_arrive[(l +  64) * 32]);
            unsigned v3 = ld_acquire(&g_arrive[(l +  96) * 32]);
            ok = __all_sync(0xffffffffu,
                            v0 >= ep && v1 >= ep && v2 >= ep && v3 >= ep);
        } while (!ok);
    }
    __syncthreads();                       // publish acquire to whole CTA
}

// ---- math helpers ------------------------------------------------------------
__device__ __forceinline__ float warp_sum(float s) {
#pragma unroll
    for (int o = 16; o; o >>= 1) s += __shfl_xor_sync(0xffffffffu, s, o);
    return s;
}

__device__ __forceinline__ void load_h_cg(const float* buf, float4 h[4], int lane) {
    const float4* b4 = reinterpret_cast<const float4*>(buf);
#pragma unroll
    for (int j = 0; j < 4; j++) h[j] = __ldcg(&b4[lane + 32 * j]);
}

// 4 register-weight row-dots vs h, interleaved butterfly allreduce.
__device__ __forceinline__ void mv4(const float4 w[4][4], const float4 h[4], float s[4]) {
#pragma unroll
    for (int g = 0; g < 4; ++g) {
        float a = 0.f;
#pragma unroll
        for (int j = 0; j < 4; ++j) {
            a = fmaf(w[g][j].x, h[j].x, a);
            a = fmaf(w[g][j].y, h[j].y, a);
            a = fmaf(w[g][j].z, h[j].z, a);
            a = fmaf(w[g][j].w, h[j].w, a);
        }
        s[g] = a;
    }
#pragma unroll
    for (int o = 16; o; o >>= 1)
#pragma unroll
        for (int g = 0; g < 4; ++g) s[g] += __shfl_xor_sync(0xffffffffu, s[g], o);
}

// 8 dots (two matrices x 4 gates), interleaved butterfly allreduce.
__device__ __forceinline__ void mv8(const float4 wa[4][4], const float4 ha[4],
                                    const float4 wb[4][4], const float4 hb[4],
                                    float s[8]) {
#pragma unroll
    for (int g = 0; g < 4; ++g) {
        float a = 0.f, b = 0.f;
#pragma unroll
        for (int j = 0; j < 4; ++j) {
            a = fmaf(wa[g][j].x, ha[j].x, a);
            a = fmaf(wa[g][j].y, ha[j].y, a);
            a = fmaf(wa[g][j].z, ha[j].z, a);
            a = fmaf(wa[g][j].w, ha[j].w, a);
            b = fmaf(wb[g][j].x, hb[j].x, b);
            b = fmaf(wb[g][j].y, hb[j].y, b);
            b = fmaf(wb[g][j].z, hb[j].z, b);
            b = fmaf(wb[g][j].w, hb[j].w, b);
        }
        s[g] = a; s[4 + g] = b;
    }
#pragma unroll
    for (int o = 16; o; o >>= 1)
#pragma unroll
        for (int g = 0; g < 8; ++g) s[g] += __shfl_xor_sync(0xffffffffu, s[g], o);
}

__device__ __forceinline__ float sigf(float x) { return 1.f / (1.f + __expf(-x)); }

__device__ __forceinline__ float cellf(float pi, float pf, float pg, float po, float& c) {
    float i_ = sigf(pi), f_ = sigf(pf), g_ = tanhf(pg), o_ = sigf(po);
    c = f_ * c + i_ * g_;
    return o_ * tanhf(c);
}

// ---- main persistent kernel ----------------------------------------------------
__global__ void __launch_bounds__(TPB, 1) lstm_main_kernel(
    const float* __restrict__ input,
    const float* __restrict__ Wih1, const float* __restrict__ Whh1,
    const float* __restrict__ bih1, const float* __restrict__ bhh1,
    const float* __restrict__ Wih2, const float* __restrict__ Whh2,
    const float* __restrict__ bih2, const float* __restrict__ bhh2,
    const float* __restrict__ Wlin, const float* __restrict__ blin,
    float* __restrict__ out)
{
    const int  lane = threadIdx.x & 31;
    const int  bid  = blockIdx.x;
    const int  gw   = bid * (TPB / 32) + (threadIdx.x >> 5);  // 0..1023
    const bool is1  = (gw < HH);
    const int  k    = is1 ? gw : gw - HH;

    // ---- one-time: this warp's weight rows -> REGISTERS ----
    float4 wA[4][4], wB[4][4];
    {
        const float4* WA = reinterpret_cast<const float4*>(is1 ? Whh1 : Whh2);
#pragma unroll
        for (int g = 0; g < 4; ++g) {
            const float4* row = WA + (size_t)(k + 512 * g) * (HH / 4);
#pragma unroll
            for (int j = 0; j < 4; ++j) wA[g][j] = __ldg(&row[lane + 32 * j]);
        }
        if (!is1) {
            const float4* WB = reinterpret_cast<const float4*>(Wih2);
#pragma unroll
            for (int g = 0; g < 4; ++g) {
                const float4* row = WB + (size_t)(k + 512 * g) * (HH / 4);
#pragma unroll
                for (int j = 0; j < 4; ++j) wB[g][j] = __ldg(&row[lane + 32 * j]);
            }
        } else {
#pragma unroll
            for (int g = 0; g < 4; ++g)
#pragma unroll
                for (int j = 0; j < 4; ++j) wB[g][j] = make_float4(0.f, 0.f, 0.f, 0.f);
        }
    }
    float4 wlin4[4];
    {
        const float4* WL = reinterpret_cast<const float4*>(Wlin);
#pragma unroll
        for (int j = 0; j < 4; ++j) wlin4[j] = __ldg(&WL[lane + 32 * j]);
    }
    float bsum[4], wx[4];
#pragma unroll
    for (int g = 0; g < 4; ++g) {
        int r = k + 512 * g;
        if (is1) { bsum[g] = __ldg(&bih1[r]) + __ldg(&bhh1[r]); wx[g] = __ldg(&Wih1[r]); }
        else     { bsum[g] = __ldg(&bih2[r]) + __ldg(&bhh2[r]); wx[g] = 0.f; }
    }
    const float blin0 = __ldg(blin);

    float cs = 0.f;          // c1 (type-1) or c2 (type-2), lane 0 of this warp
    unsigned ep = 0u;

    // ================= ENCODE: pipelined, ONE barrier per step =================
    // interval t: type-1 computes h1[t]; type-2 computes h2[t-1].
    for (int t = 0; t < T_ENC; ++t) {
        if (is1) {
            float x = __ldg(&input[255 * T_ENC + t]);
            float4 hr[4];
            load_h_cg(g_h1[t & 1], hr, lane);              // h1[t-1]
            float s[4];
            mv4(wA, hr, s);
            if (lane == 0) {
                float h = cellf(s[0] + bsum[0] + wx[0] * x,
                                s[1] + bsum[1] + wx[1] * x,
                                s[2] + bsum[2] + wx[2] * x,
                                s[3] + bsum[3] + wx[3] * x, cs);
                __stcg(&g_h1[(t + 1) & 1][k], h);          // h1[t]
            }
        } else if (t >= 1) {
            float4 h1r[4], h2r[4];
            load_h_cg(g_h1[t & 1], h1r, lane);             // h1[t-1]
            load_h_cg(g_h2[(t - 1) & 1], h2r, lane);       // h2[t-2]
            float s[8];
            mv8(wA, h2r, wB, h1r, s);                      // Whh2 dots, Wih2 dots
            if (lane == 0) {
                float h = cellf(s[0] + s[4] + bsum[0],
                                s[1] + s[5] + bsum[1],
                                s[2] + s[6] + bsum[2],
                                s[3] + s[7] + bsum[3], cs);
                __stcg(&g_h2[t & 1][k], h);                // h2[t-1]
            }
        }
        grid_sync(ep, bid);
    }

    // ================= DRAIN: compute h2[1023] =================
    if (!is1) {
        float4 h1r[4], h2r[4];
        load_h_cg(g_h1[T_ENC & 1], h1r, lane);             // h1[1023]
        load_h_cg(g_h2[(T_ENC - 1) & 1], h2r, lane);       // h2[1022]
        float s[8];
        mv8(wA, h2r, wB, h1r, s);
        if (lane == 0) {
            float h = cellf(s[0] + s[4] + bsum[0],
                            s[1] + s[5] + bsum[1],
                            s[2] + s[6] + bsum[2],
                            s[3] + s[7] + bsum[3], cs);
            __stcg(&g_h2[T_ENC & 1][k], h);                // h2[1023]
        }
    }
    grid_sync(ep, bid);

    // ================= AR DECODE: t = 1024 .. 1086, two barriers/step ==========
    for (int t = T_ENC; t < T_ENC + PRED - 1; ++t) {
        float sA[4];
        if (is1) {
            // y(t-1) = Wlin . h2[t-1] + blin  (h2[t-1] in g_h2[t&1])
            float4 h2r[4];
            load_h_cg(g_h2[t & 1], h2r, lane);
            float y = 0.f;
#pragma unroll
            for (int j = 0; j < 4; ++j) {
                y = fmaf(wlin4[j].x, h2r[j].x, y);
                y = fmaf(wlin4[j].y, h2r[j].y, y);
                y = fmaf(wlin4[j].z, h2r[j].z, y);
                y = fmaf(wlin4[j].w, h2r[j].w, y);
            }
            y = warp_sum(y) + blin0;
            if (gw == 0 && lane == 0) out[t - T_ENC] = y;  // out[0..62]
            float x = y;   // bitwise identical in all warps
            float4 hr[4];
            load_h_cg(g_h1[t & 1], hr, lane);              // h1[t-1]
            float s[4];
            mv4(wA, hr, s);
            if (lane == 0) {
                float h = cellf(s[0] + bsum[0] + wx[0] * x,
                                s[1] + bsum[1] + wx[1] * x,
                                s[2] + bsum[2] + wx[2] * x,
                                s[3] + bsum[3] + wx[3] * x, cs);
                __stcg(&g_h1[(t + 1) & 1][k], h);          // h1[t]
            }
        } else {
            float4 h2r[4];
            load_h_cg(g_h2[t & 1], h2r, lane);             // h2[t-1]
            mv4(wA, h2r, sA);                              // Whh2 partials stay in regs
        }
        grid_sync(ep, bid);

        if (!is1) {
            float4 h1r[4];
            load_h_cg(g_h1[(t + 1) & 1], h1r, lane);       // h1[t]
            float s[4];
            mv4(wB, h1r, s);
            if (lane == 0) {
                float h = cellf(sA[0] + s[0] + bsum[0],
                                sA[1] + s[1] + bsum[1],
                                sA[2] + s[2] + bsum[2],
                                sA[3] + s[3] + bsum[3], cs);
                __stcg(&g_h2[(t + 1) & 1][k], h);          // h2[t]
            }
        }
        grid_sync(ep, bid);
    }

    // ================= EPILOGUE: out[63] = Wlin . h2[1086] + blin ==============
    if (gw == 0) {
        float4 h2r[4];
        load_h_cg(g_h2[(T_ENC + PRED - 1) & 1], h2r, lane); // h2[1086]
        float y = 0.f;
#pragma unroll
        for (int j = 0; j < 4; ++j) {
            y = fmaf(wlin4[j].x, h2r[j].x, y);
            y = fmaf(wlin4[j].y, h2r[j].y, y);
            y = fmaf(wlin4[j].z, h2r[j].z, y);
            y = fmaf(wlin4[j].w, h2r[j].w, y);
        }
        y = warp_sum(y) + blin0;
        if (lane == 0) out[PRED - 1] = y;
    }
}

// ---------------------------------------------------------------------------
// inputs (metadata order): 0 input(256x1024 f32), 1 pred_len(i32, =64),
// 2 Wih1(2048x1), 3 Whh1(2048x512), 4 bih1(2048), 5 bhh1(2048),
// 6 Wih2(2048x512), 7 Whh2(2048x512), 8 bih2(2048), 9 bhh2(2048),
// 10 Wlin(1x512), 11 blin(1).  output: 64 f32.
// ---------------------------------------------------------------------------
extern "C" void kernel_launch(void* const* d_in, const int* in_sizes, int n_in,
                              void* d_out, int out_size) {
    (void)in_sizes; (void)n_in; (void)out_size;
    const float* input = (const float*)d_in[0];
    const float* Wih1  = (const float*)d_in[2];
    const float* Whh1  = (const float*)d_in[3];
    const float* bih1  = (const float*)d_in[4];
    const float* bhh1  = (const float*)d_in[5];
    const float* Wih2  = (const float*)d_in[6];
    const float* Whh2  = (const float*)d_in[7];
    const float* bih2  = (const float*)d_in[8];
    const float* bhh2  = (const float*)d_in[9];
    const float* Wlin  = (const float*)d_in[10];
    const float* blin  = (const float*)d_in[11];

    lstm_init_kernel<<<1, 256>>>();
    lstm_main_kernel<<<GRID, TPB>>>(input, Wih1, Whh1, bih1, bhh1,
                                    Wih2, Whh2, bih2, bhh2,
                                    Wlin, blin, (float*)d_out);
}